// round 15
// baseline (speedup 1.0000x reference)
#include <cuda_runtime.h>
#include <cuda_fp16.h>
#include <math.h>
#include <stdint.h>

#define B_ 4
#define T_ 2048
#define E_ 512
#define H_ 8
// (1/sqrt(512)) * log2(e)
#define SCALE_LOG2E 0.06375872468f

// Scratch (device globals; allocation-free per harness rules)
__device__ __half g_xh [B_ * T_ * E_];
__device__ __half g_ch [B_ * T_ * E_];
__device__ __half g_Wh [4 * E_ * E_];
__device__ __half g_Qh [B_ * T_ * E_];
__device__ __half g_Kh [B_ * T_ * E_];
__device__ __half g_Vth[B_ * H_ * 64 * T_];  // V^T per head: [bh][s=64][c=2048]
__device__ __half g_Oh [B_ * T_ * E_];

// ---------------------------------------------------------------------------
// helpers (compute_103-safe: mma.sync + cp.async + ldmatrix, no tcgen05)
// ---------------------------------------------------------------------------
__device__ __forceinline__ uint32_t cvta_s(const void* p) {
    uint32_t a;
    asm("{ .reg .u64 t; cvta.to.shared.u64 t, %1; cvt.u32.u64 %0, t; }"
        : "=r"(a) : "l"(p));
    return a;
}
__device__ __forceinline__ float ex2(float x) {
    float r; asm("ex2.approx.f32 %0, %1;" : "=f"(r) : "f"(x)); return r;
}
__device__ __forceinline__ uint32_t packh2(float lo, float hi) {
    __half2 h = __floats2half2_rn(lo, hi);
    return *(uint32_t*)&h;
}
__device__ __forceinline__ void cp16(uint32_t dst, const void* src) {
    uint64_t g;
    asm("cvta.to.global.u64 %0, %1;" : "=l"(g) : "l"(src));
    asm volatile("cp.async.cg.shared.global [%0], [%1], 16;"
                 :: "r"(dst), "l"(g));
}
__device__ __forceinline__ void cp_commit() {
    asm volatile("cp.async.commit_group;");
}
__device__ __forceinline__ void cp_wait0() {
    asm volatile("cp.async.wait_group 0;");
}
__device__ __forceinline__ void cp_wait1() {
    asm volatile("cp.async.wait_group 1;");
}
__device__ __forceinline__ void cp_wait2() {
    asm volatile("cp.async.wait_group 2;");
}
__device__ __forceinline__ void ldsm4(uint32_t& r0, uint32_t& r1,
                                      uint32_t& r2, uint32_t& r3, uint32_t addr) {
    asm volatile("ldmatrix.sync.aligned.m8n8.x4.shared.b16 {%0,%1,%2,%3}, [%4];"
                 : "=r"(r0), "=r"(r1), "=r"(r2), "=r"(r3) : "r"(addr));
}
// fp16 m16n8k16
__device__ __forceinline__ void mma16h(float& d0, float& d1, float& d2, float& d3,
                                       uint32_t a0, uint32_t a1, uint32_t a2, uint32_t a3,
                                       uint32_t b0, uint32_t b1) {
    asm volatile(
        "mma.sync.aligned.m16n8k16.row.col.f32.f16.f16.f32 "
        "{%0,%1,%2,%3}, {%4,%5,%6,%7}, {%8,%9}, {%0,%1,%2,%3};"
        : "+f"(d0), "+f"(d1), "+f"(d2), "+f"(d3)
        : "r"(a0), "r"(a1), "r"(a2), "r"(a3), "r"(b0), "r"(b1));
}

// ---------------------------------------------------------------------------
// fp32 -> fp16 conversion prepass (2 launches)
// ---------------------------------------------------------------------------
__global__ void cvt2(const float4* __restrict__ a, uint2* __restrict__ oa,
                     const float4* __restrict__ b, uint2* __restrict__ ob,
                     int n4each) {
    int i = blockIdx.x * blockDim.x + threadIdx.x;
    const float4* src; uint2* dst; int j;
    if (i < n4each) { src = a; dst = oa; j = i; }
    else            { src = b; dst = ob; j = i - n4each; }
    float4 v = src[j];
    dst[j] = make_uint2(packh2(v.x, v.y), packh2(v.z, v.w));
}
__global__ void cvt4(const float4* __restrict__ a, const float4* __restrict__ b,
                     const float4* __restrict__ c, const float4* __restrict__ d,
                     uint2* __restrict__ o, int n4each) {
    int i = blockIdx.x * blockDim.x + threadIdx.x;
    int which = i / n4each, j = i - which * n4each;
    const float4* src = (which == 0) ? a : (which == 1) ? b : (which == 2) ? c : d;
    float4 v = src[j];
    o[i] = make_uint2(packh2(v.x, v.y), packh2(v.z, v.w));
}

// ---------------------------------------------------------------------------
// fp16 GEMM: C[M,512] = A[M,512] @ W[512,512]^T (+bias).
// 128x128 CTA tile, BK=64 halves double-buffered, 8 warps x (64x32) tiles.
// gridDim.z==3 (QKV): epilogues emit fp16 -> Qh / Kh / Vth (V transposed).
// bias != null (out-projection): fp32 + bias -> Cf.
// ---------------------------------------------------------------------------
#define GPH 72
__global__ __launch_bounds__(256, 2) void gemm_h(
    const __half* __restrict__ A0, const __half* __restrict__ A1,
    const __half* __restrict__ Wb, const float* __restrict__ bias,
    float* __restrict__ Cf, __half* __restrict__ Qh,
    __half* __restrict__ Kh, __half* __restrict__ Vth)
{
    extern __shared__ char smc[];
    const uint32_t sAu = cvta_s(smc);
    const uint32_t sBu = sAu + 2 * 128 * GPH * 2;

    const int z = blockIdx.z;
    const __half* A = (z == 0) ? A0 : A1;
    const __half* W = Wb + (size_t)z * E_ * E_;

    const int tid = threadIdx.x, lane = tid & 31, w = tid >> 5;
    const int wm = w & 1, wn = w >> 1;
    const int r4 = lane >> 2, cc = lane & 3;
    const int lr = lane & 7, gq = lane >> 3;
    const int bm = blockIdx.y * 128, bn = blockIdx.x * 128;
    const __half* Ag = A + (size_t)bm * E_;
    const __half* Bg = W + (size_t)bn * E_;

    uint32_t aoff[4], boff[2];
#pragma unroll
    for (int mi = 0; mi < 4; mi++)
        aoff[mi] = (uint32_t)(((wm * 64 + mi * 16 + (gq & 1) * 8 + lr) * GPH
                              + (gq >> 1) * 8) * 2);
#pragma unroll
    for (int np = 0; np < 2; np++)
        boff[np] = (uint32_t)(((wn * 32 + np * 16 + (gq >> 1) * 8 + lr) * GPH
                              + (gq & 1) * 8) * 2);

    float acc[4][4][4];
#pragma unroll
    for (int mi = 0; mi < 4; mi++)
#pragma unroll
        for (int ni = 0; ni < 4; ni++)
#pragma unroll
            for (int j = 0; j < 4; j++) acc[mi][ni][j] = 0.f;

#pragma unroll
    for (int i = 0; i < 4; i++) {
        int f = tid + i * 256, row = f >> 3, c8 = f & 7;
        cp16(sAu + (uint32_t)(row * GPH + c8 * 8) * 2, Ag + (size_t)row * E_ + c8 * 8);
        cp16(sBu + (uint32_t)(row * GPH + c8 * 8) * 2, Bg + (size_t)row * E_ + c8 * 8);
    }
    cp_commit();

    for (int ks = 0; ks < 8; ks++) {
        cp_wait0();
        __syncthreads();
        if (ks < 7) {
            int k0 = (ks + 1) * 64, buf = (ks + 1) & 1;
#pragma unroll
            for (int i = 0; i < 4; i++) {
                int f = tid + i * 256, row = f >> 3, c8 = f & 7;
                uint32_t so = (uint32_t)((buf * 128 + row) * GPH + c8 * 8) * 2;
                cp16(sAu + so, Ag + (size_t)row * E_ + k0 + c8 * 8);
                cp16(sBu + so, Bg + (size_t)row * E_ + k0 + c8 * 8);
            }
            cp_commit();
        }
        const uint32_t abuf = sAu + (uint32_t)(ks & 1) * 128 * GPH * 2;
        const uint32_t bbuf = sBu + (uint32_t)(ks & 1) * 128 * GPH * 2;
#pragma unroll
        for (int kk = 0; kk < 4; kk++) {
            uint32_t af[4][4], bf[4][2];
#pragma unroll
            for (int mi = 0; mi < 4; mi++)
                ldsm4(af[mi][0], af[mi][1], af[mi][2], af[mi][3],
                      abuf + aoff[mi] + kk * 32);
#pragma unroll
            for (int np = 0; np < 2; np++)
                ldsm4(bf[np * 2][0], bf[np * 2][1], bf[np * 2 + 1][0], bf[np * 2 + 1][1],
                      bbuf + boff[np] + kk * 32);
#pragma unroll
            for (int mi = 0; mi < 4; mi++)
#pragma unroll
                for (int ni = 0; ni < 4; ni++)
                    mma16h(acc[mi][ni][0], acc[mi][ni][1], acc[mi][ni][2], acc[mi][ni][3],
                           af[mi][0], af[mi][1], af[mi][2], af[mi][3],
                           bf[ni][0], bf[ni][1]);
        }
    }

    if (bias) {
#pragma unroll
        for (int mi = 0; mi < 4; mi++) {
            int row = bm + wm * 64 + mi * 16 + r4;
#pragma unroll
            for (int ni = 0; ni < 4; ni++) {
                int col = bn + wn * 32 + ni * 8 + 2 * cc;
                float b0 = bias[col], b1 = bias[col + 1];
                *(float2*)(Cf + (size_t)row * E_ + col) =
                    make_float2(acc[mi][ni][0] + b0, acc[mi][ni][1] + b1);
                *(float2*)(Cf + (size_t)(row + 8) * E_ + col) =
                    make_float2(acc[mi][ni][2] + b0, acc[mi][ni][3] + b1);
            }
        }
    } else if (z == 2) {
#pragma unroll
        for (int mi = 0; mi < 4; mi++) {
            int tok = bm + wm * 64 + mi * 16 + r4;
            int bb = tok >> 11, tt = tok & 2047;
#pragma unroll
            for (int ni = 0; ni < 4; ni++) {
                int f = bn + wn * 32 + ni * 8 + 2 * cc;
                int head = f >> 6, nl = f & 63;
                __half* p = Vth + ((size_t)(bb * 8 + head) * 64 + nl) * 2048 + tt;
                p[0]        = __float2half_rn(acc[mi][ni][0]);
                p[2048]     = __float2half_rn(acc[mi][ni][1]);
                p[8]        = __float2half_rn(acc[mi][ni][2]);
                p[2048 + 8] = __float2half_rn(acc[mi][ni][3]);
            }
        }
    } else {
        __half* CH = (z == 0) ? Qh : Kh;
#pragma unroll
        for (int mi = 0; mi < 4; mi++) {
            int row = bm + wm * 64 + mi * 16 + r4;
#pragma unroll
            for (int ni = 0; ni < 4; ni++) {
                int col = bn + wn * 32 + ni * 8 + 2 * cc;
                __half2 h0 = __floats2half2_rn(acc[mi][ni][0], acc[mi][ni][1]);
                __half2 h1 = __floats2half2_rn(acc[mi][ni][2], acc[mi][ni][3]);
                *(__half2*)(CH + (size_t)row * E_ + col)       = h0;
                *(__half2*)(CH + (size_t)(row + 8) * E_ + col) = h1;
            }
        }
    }
}

// ---------------------------------------------------------------------------
// Fused attention, fp16 mma m16n8k16.  CTA = 64 queries of one (b,h).
// Warp grid 4(m) x 2(n), split-k PV, direct exp->fp16 A-fragment pack.
// DEPTH-2 cp.async pipeline: 3-buffer K/V ring, wait_group 1 at the top of
// each iteration (tile ct complete, tile ct+1 still in flight).  Exactly one
// group committed per iteration (empty near the end) keeps group counts exact.
// ---------------------------------------------------------------------------
#define APH 72
__global__ __launch_bounds__(256) void attn_tc(const int* __restrict__ mask)
{
    extern __shared__ char smc[];
    __half* sQ = (__half*)smc;                   // 64*72  (9216 B)
    __half* sK = (__half*)(smc + 9216);          // 3*64*72 (27648 B)
    __half* sV = (__half*)(smc + 36864);         // 3*64*72 (27648 B)
    float*  sO = (float*)(smc + 64512);          // 64*68 fp32 (17408 B)
    __shared__ float sL[64][2];

    const int tid = threadIdx.x, lane = tid & 31, w = tid >> 5;
    const int wm = w & 3, wn = w >> 2;           // 4(m) x 2(n)
    const int r4 = lane >> 2, cc = lane & 3;
    const int lr = lane & 7, gq = lane >> 3;
    const int qt = blockIdx.x, bh = blockIdx.y;
    const int b = bh >> 3, h = bh & 7;
    const uint32_t sQu = cvta_s(sQ), sKu = cvta_s(sK), sVu = cvta_s(sV);

    const __half* Qg  = g_Qh  + ((size_t)(b * T_ + qt * 64)) * E_ + h * 64;
    const __half* Kg  = g_Kh  + ((size_t)b * T_) * E_ + h * 64;
    const __half* Vtg = g_Vth + (size_t)bh * 64 * T_;

    uint32_t koff[2];
#pragma unroll
    for (int np = 0; np < 2; np++)
        koff[np] = (uint32_t)(((wn * 32 + np * 16 + (gq >> 1) * 8 + lr) * APH
                              + (gq & 1) * 8) * 2);
    uint32_t voff[4];
#pragma unroll
    for (int np = 0; np < 4; np++)
        voff[np] = (uint32_t)(((np * 16 + (gq >> 1) * 8 + lr) * APH
                              + wn * 32 + (gq & 1) * 8) * 2);
    const uint32_t qoff = (uint32_t)(((wm * 16 + (gq & 1) * 8 + lr) * APH
                                     + (gq >> 1) * 8) * 2);

    // group 0: Q tile (64 x 64 halves)
#pragma unroll
    for (int i = 0; i < 2; i++) {
        int f = tid + i * 256, row = f >> 3, c8 = f & 7;
        cp16(sQu + (uint32_t)(row * APH + c8 * 8) * 2, Qg + (size_t)row * E_ + c8 * 8);
    }
    cp_commit();
    // groups 1,2: K/V tiles 0 and 1 into ring buffers 0,1
#pragma unroll
    for (int t = 0; t < 2; t++) {
#pragma unroll
        for (int i = 0; i < 2; i++) {
            int f = tid + i * 256, row = f >> 3, c8 = f & 7;
            uint32_t so = (uint32_t)((t * 64 + row) * APH + c8 * 8) * 2;
            cp16(sKu + so, Kg  + (size_t)(t * 64 + row) * E_ + c8 * 8);
            cp16(sVu + so, Vtg + (size_t)row * T_ + t * 64 + c8 * 8);
        }
        cp_commit();
    }

    const int* mrow = mask + (size_t)bh * T_ + qt * 64 + wm * 16;
    float madd[2];
    madd[0] = mrow[r4]     ? 0.f : -INFINITY;
    madd[1] = mrow[r4 + 8] ? 0.f : -INFINITY;

    cp_wait2();        // Q done (tiles 0,1 may still be in flight)
    __syncthreads();
    uint32_t qf[4][4];
#pragma unroll
    for (int kk = 0; kk < 4; kk++)
        ldsm4(qf[kk][0], qf[kk][1], qf[kk][2], qf[kk][3], sQu + qoff + kk * 32);

    float oAcc[8][4];
    float lsum[2] = {0.f, 0.f};
#pragma unroll
    for (int ni = 0; ni < 8; ni++)
#pragma unroll
        for (int j = 0; j < 4; j++) oAcc[ni][j] = 0.f;

    for (int ct = 0; ct < 32; ct++) {
        cp_wait1();        // tile ct landed; tile ct+1 may still be in flight
        __syncthreads();   // all warps done reading buffer (ct+2)%3 (iter ct-1)
        {
            int pf = ct + 2;
            if (pf < 32) {
                int buf = pf % 3;
                const __half* Kp = Kg  + (size_t)pf * 64 * E_;
                const __half* Vp = Vtg + (size_t)pf * 64;
#pragma unroll
                for (int i = 0; i < 2; i++) {
                    int f = tid + i * 256, row = f >> 3, c8 = f & 7;
                    uint32_t so = (uint32_t)((buf * 64 + row) * APH + c8 * 8) * 2;
                    cp16(sKu + so, Kp + (size_t)row * E_ + c8 * 8);
                    cp16(sVu + so, Vp + (size_t)row * T_ + c8 * 8);
                }
            }
            cp_commit();   // exactly one group per iteration (possibly empty)
        }
        const uint32_t kbu = sKu + (uint32_t)(ct % 3) * 64 * APH * 2;
        const uint32_t vbu = sVu + (uint32_t)(ct % 3) * 64 * APH * 2;

        // ---- S = Q @ K^T (m64 n64 k64)
        float sAcc[4][4];
#pragma unroll
        for (int ni = 0; ni < 4; ni++)
#pragma unroll
            for (int j = 0; j < 4; j++) sAcc[ni][j] = 0.f;

#pragma unroll
        for (int kk = 0; kk < 4; kk++) {
            uint32_t bf[4][2];
#pragma unroll
            for (int np = 0; np < 2; np++)
                ldsm4(bf[np * 2][0], bf[np * 2][1], bf[np * 2 + 1][0], bf[np * 2 + 1][1],
                      kbu + koff[np] + kk * 32);
#pragma unroll
            for (int ni = 0; ni < 4; ni++)
                mma16h(sAcc[ni][0], sAcc[ni][1], sAcc[ni][2], sAcc[ni][3],
                       qf[kk][0], qf[kk][1], qf[kk][2], qf[kk][3],
                       bf[ni][0], bf[ni][1]);
        }

        // ---- exp + direct fp16 pack (acc layout == A-frag layout)
        uint32_t pa[4][2];
#pragma unroll
        for (int nb = 0; nb < 4; nb++) {
            float p0 = ex2(fmaf(sAcc[nb][0], SCALE_LOG2E, madd[0]));
            float p1 = ex2(fmaf(sAcc[nb][1], SCALE_LOG2E, madd[0]));
            float p2 = ex2(fmaf(sAcc[nb][2], SCALE_LOG2E, madd[1]));
            float p3 = ex2(fmaf(sAcc[nb][3], SCALE_LOG2E, madd[1]));
            lsum[0] += p0 + p1;
            lsum[1] += p2 + p3;
            pa[nb][0] = packh2(p0, p1);
            pa[nb][1] = packh2(p2, p3);
        }

        // ---- O += P @ V (split-k: warp's 32 context cols = 2 k16 steps)
#pragma unroll
        for (int kb = 0; kb < 2; kb++) {
            uint32_t bf[8][2];
#pragma unroll
            for (int np = 0; np < 4; np++)
                ldsm4(bf[np * 2][0], bf[np * 2][1], bf[np * 2 + 1][0], bf[np * 2 + 1][1],
                      vbu + voff[np] + kb * 32);
            uint32_t a0 = pa[2 * kb][0],     a1 = pa[2 * kb][1];
            uint32_t a2 = pa[2 * kb + 1][0], a3 = pa[2 * kb + 1][1];
#pragma unroll
            for (int ni = 0; ni < 8; ni++)
                mma16h(oAcc[ni][0], oAcc[ni][1], oAcc[ni][2], oAcc[ni][3],
                       a0, a1, a2, a3, bf[ni][0], bf[ni][1]);
        }
    }

    // ---- l reduction (quad lanes) -> sL[row][wn]
#pragma unroll
    for (int rr = 0; rr < 2; rr++) {
        float s = lsum[rr];
        s += __shfl_xor_sync(0xffffffffu, s, 1);
        s += __shfl_xor_sync(0xffffffffu, s, 2);
        if (cc == 0) sL[wm * 16 + r4 + rr * 8][wn] = s;
    }

    // ---- cross-wn O reduction via fp32 smem
    if (wn == 1) {
        int row = wm * 16 + r4;
#pragma unroll
        for (int ni = 0; ni < 8; ni++) {
            *(float2*)(sO + row * 68 + ni * 8 + 2 * cc) =
                make_float2(oAcc[ni][0], oAcc[ni][1]);
            *(float2*)(sO + (row + 8) * 68 + ni * 8 + 2 * cc) =
                make_float2(oAcc[ni][2], oAcc[ni][3]);
        }
    }
    __syncthreads();

    if (wn == 0) {
        __half* Og = g_Oh + ((size_t)(b * T_ + qt * 64)) * E_ + h * 64;
        int row = wm * 16 + r4;
        float inv0 = 1.f / (sL[row][0] + sL[row][1]);
        float inv1 = 1.f / (sL[row + 8][0] + sL[row + 8][1]);
#pragma unroll
        for (int ni = 0; ni < 8; ni++) {
            float2 q0 = *(float2*)(sO + row * 68 + ni * 8 + 2 * cc);
            float2 q1 = *(float2*)(sO + (row + 8) * 68 + ni * 8 + 2 * cc);
            int col = ni * 8 + 2 * cc;
            *(__half2*)(Og + (size_t)row * E_ + col) =
                __floats2half2_rn((oAcc[ni][0] + q0.x) * inv0,
                                  (oAcc[ni][1] + q0.y) * inv0);
            *(__half2*)(Og + (size_t)(row + 8) * E_ + col) =
                __floats2half2_rn((oAcc[ni][2] + q1.x) * inv1,
                                  (oAcc[ni][3] + q1.y) * inv1);
        }
    }
}

// ---------------------------------------------------------------------------
extern "C" void kernel_launch(void* const* d_in, const int* in_sizes, int n_in,
                              void* d_out, int out_size)
{
    const float* x    = (const float*)d_in[0];
    const float* ctx  = (const float*)d_in[1];
    const int*   mask = (const int*)d_in[2];
    const float* Wq   = (const float*)d_in[3];
    const float* Wk   = (const float*)d_in[4];
    const float* Wv   = (const float*)d_in[5];
    const float* Wu   = (const float*)d_in[6];
    const float* bu   = (const float*)d_in[7];
    float* out = (float*)d_out;

    __half *pxh, *pch, *pWh, *pQh, *pKh, *pVth, *pOh;
    cudaGetSymbolAddress((void**)&pxh,  g_xh);
    cudaGetSymbolAddress((void**)&pch,  g_ch);
    cudaGetSymbolAddress((void**)&pWh,  g_Wh);
    cudaGetSymbolAddress((void**)&pQh,  g_Qh);
    cudaGetSymbolAddress((void**)&pKh,  g_Kh);
    cudaGetSymbolAddress((void**)&pVth, g_Vth);
    cudaGetSymbolAddress((void**)&pOh,  g_Oh);

    const int NX = B_ * T_ * E_ / 4;
    const int NW = E_ * E_ / 4;
    cvt2<<<2 * NX / 256, 256>>>((const float4*)x, (uint2*)pxh,
                                (const float4*)ctx, (uint2*)pch, NX);
    cvt4<<<4 * NW / 256, 256>>>((const float4*)Wq, (const float4*)Wk,
                                (const float4*)Wv, (const float4*)Wu,
                                (uint2*)pWh, NW);

    const int SMEM_G = 4 * 128 * GPH * 2;                      // 73728
    const int SMEM_A = 64512 + 64 * 68 * 4;                    // 81920
    cudaFuncSetAttribute(gemm_h,  cudaFuncAttributeMaxDynamicSharedMemorySize, SMEM_G);
    cudaFuncSetAttribute(attn_tc, cudaFuncAttributeMaxDynamicSharedMemorySize, SMEM_A);

    // merged Q/K/V projections (fp16; z=2 writes V^T)
    dim3 gQKV(E_ / 128, B_ * T_ / 128, 3);
    gemm_h<<<gQKV, 256, SMEM_G>>>(pxh, pch, pWh, nullptr, nullptr, pQh, pKh, pVth);

    dim3 gA(T_ / 64, B_ * H_);   // (32, 32)
    attn_tc<<<gA, 256, SMEM_A>>>(mask);

    // output projection (fp32 + bias)
    dim3 gO(E_ / 128, B_ * T_ / 128, 1);
    gemm_h<<<gO, 256, SMEM_G>>>(pOh, nullptr, pWh + 3 * E_ * E_, bu, out,
                                nullptr, nullptr, nullptr);
}

// round 16
// speedup vs baseline: 1.1009x; 1.1009x over previous
#include <cuda_runtime.h>
#include <cuda_fp16.h>
#include <math.h>
#include <stdint.h>

#define B_ 4
#define T_ 2048
#define E_ 512
#define H_ 8
// (1/sqrt(512)) * log2(e)
#define SCALE_LOG2E 0.06375872468f

// Scratch (device globals; allocation-free per harness rules)
__device__ __half g_xh [B_ * T_ * E_];
__device__ __half g_ch [B_ * T_ * E_];
__device__ __half g_Wh [4 * E_ * E_];
__device__ __half g_Qh [B_ * T_ * E_];
__device__ __half g_Kh [B_ * T_ * E_];
__device__ __half g_Vth[B_ * H_ * 64 * T_];  // V^T per head: [bh][s=64][c=2048]
__device__ __half g_Oh [B_ * T_ * E_];

// ---------------------------------------------------------------------------
// helpers (compute_103-safe: mma.sync + cp.async + ldmatrix, no tcgen05)
// ---------------------------------------------------------------------------
__device__ __forceinline__ uint32_t cvta_s(const void* p) {
    uint32_t a;
    asm("{ .reg .u64 t; cvta.to.shared.u64 t, %1; cvt.u32.u64 %0, t; }"
        : "=r"(a) : "l"(p));
    return a;
}
__device__ __forceinline__ float ex2(float x) {
    float r; asm("ex2.approx.f32 %0, %1;" : "=f"(r) : "f"(x)); return r;
}
__device__ __forceinline__ uint32_t packh2(float lo, float hi) {
    __half2 h = __floats2half2_rn(lo, hi);
    return *(uint32_t*)&h;
}
__device__ __forceinline__ void cp16(uint32_t dst, const void* src) {
    uint64_t g;
    asm("cvta.to.global.u64 %0, %1;" : "=l"(g) : "l"(src));
    asm volatile("cp.async.cg.shared.global [%0], [%1], 16;"
                 :: "r"(dst), "l"(g));
}
__device__ __forceinline__ void cp_commit() {
    asm volatile("cp.async.commit_group;");
}
__device__ __forceinline__ void cp_wait0() {
    asm volatile("cp.async.wait_group 0;");
}
__device__ __forceinline__ void cp_wait1() {
    asm volatile("cp.async.wait_group 1;");
}
__device__ __forceinline__ void ldsm4(uint32_t& r0, uint32_t& r1,
                                      uint32_t& r2, uint32_t& r3, uint32_t addr) {
    asm volatile("ldmatrix.sync.aligned.m8n8.x4.shared.b16 {%0,%1,%2,%3}, [%4];"
                 : "=r"(r0), "=r"(r1), "=r"(r2), "=r"(r3) : "r"(addr));
}
// fp16 m16n8k16
__device__ __forceinline__ void mma16h(float& d0, float& d1, float& d2, float& d3,
                                       uint32_t a0, uint32_t a1, uint32_t a2, uint32_t a3,
                                       uint32_t b0, uint32_t b1) {
    asm volatile(
        "mma.sync.aligned.m16n8k16.row.col.f32.f16.f16.f32 "
        "{%0,%1,%2,%3}, {%4,%5,%6,%7}, {%8,%9}, {%0,%1,%2,%3};"
        : "+f"(d0), "+f"(d1), "+f"(d2), "+f"(d3)
        : "r"(a0), "r"(a1), "r"(a2), "r"(a3), "r"(b0), "r"(b1));
}

// ---------------------------------------------------------------------------
// fp32 -> fp16 conversion prepass: ONE launch for x, ctx, and all 4 weights.
// ---------------------------------------------------------------------------
__global__ void cvt_all(const float4* __restrict__ x,  uint2* __restrict__ ox,
                        const float4* __restrict__ c,  uint2* __restrict__ oc,
                        const float4* __restrict__ w0, const float4* __restrict__ w1,
                        const float4* __restrict__ w2, const float4* __restrict__ w3,
                        uint2* __restrict__ ow, int nx, int nw) {
    int i = blockIdx.x * blockDim.x + threadIdx.x;
    const float4* src; uint2* dst; int j;
    if (i < nx)            { src = x;  dst = ox; j = i; }
    else if (i < 2 * nx)   { src = c;  dst = oc; j = i - 2 * nx + nx; }
    else {
        int k = i - 2 * nx;          // 0 .. 4*nw-1
        int which = k / nw;  j = k - which * nw;
        src = (which == 0) ? w0 : (which == 1) ? w1 : (which == 2) ? w2 : w3;
        dst = ow + (size_t)which * nw;
    }
    float4 v = src[j];
    dst[j] = make_uint2(packh2(v.x, v.y), packh2(v.z, v.w));
}

// ---------------------------------------------------------------------------
// fp16 GEMM: C[M,512] = A[M,512] @ W[512,512]^T (+bias).
// 128x128 CTA tile, BK=64 halves double-buffered, 8 warps x (64x32) tiles.
// gridDim.z==3 (QKV): epilogues emit fp16 -> Qh / Kh / Vth (V transposed).
// bias != null (out-projection): fp32 + bias -> Cf.
// ---------------------------------------------------------------------------
#define GPH 72
__global__ __launch_bounds__(256, 2) void gemm_h(
    const __half* __restrict__ A0, const __half* __restrict__ A1,
    const __half* __restrict__ Wb, const float* __restrict__ bias,
    float* __restrict__ Cf, __half* __restrict__ Qh,
    __half* __restrict__ Kh, __half* __restrict__ Vth)
{
    extern __shared__ char smc[];
    const uint32_t sAu = cvta_s(smc);
    const uint32_t sBu = sAu + 2 * 128 * GPH * 2;

    const int z = blockIdx.z;
    const __half* A = (z == 0) ? A0 : A1;
    const __half* W = Wb + (size_t)z * E_ * E_;

    const int tid = threadIdx.x, lane = tid & 31, w = tid >> 5;
    const int wm = w & 1, wn = w >> 1;
    const int r4 = lane >> 2, cc = lane & 3;
    const int lr = lane & 7, gq = lane >> 3;
    const int bm = blockIdx.y * 128, bn = blockIdx.x * 128;
    const __half* Ag = A + (size_t)bm * E_;
    const __half* Bg = W + (size_t)bn * E_;

    uint32_t aoff[4], boff[2];
#pragma unroll
    for (int mi = 0; mi < 4; mi++)
        aoff[mi] = (uint32_t)(((wm * 64 + mi * 16 + (gq & 1) * 8 + lr) * GPH
                              + (gq >> 1) * 8) * 2);
#pragma unroll
    for (int np = 0; np < 2; np++)
        boff[np] = (uint32_t)(((wn * 32 + np * 16 + (gq >> 1) * 8 + lr) * GPH
                              + (gq & 1) * 8) * 2);

    float acc[4][4][4];
#pragma unroll
    for (int mi = 0; mi < 4; mi++)
#pragma unroll
        for (int ni = 0; ni < 4; ni++)
#pragma unroll
            for (int j = 0; j < 4; j++) acc[mi][ni][j] = 0.f;

#pragma unroll
    for (int i = 0; i < 4; i++) {
        int f = tid + i * 256, row = f >> 3, c8 = f & 7;
        cp16(sAu + (uint32_t)(row * GPH + c8 * 8) * 2, Ag + (size_t)row * E_ + c8 * 8);
        cp16(sBu + (uint32_t)(row * GPH + c8 * 8) * 2, Bg + (size_t)row * E_ + c8 * 8);
    }
    cp_commit();

    for (int ks = 0; ks < 8; ks++) {
        cp_wait0();
        __syncthreads();
        if (ks < 7) {
            int k0 = (ks + 1) * 64, buf = (ks + 1) & 1;
#pragma unroll
            for (int i = 0; i < 4; i++) {
                int f = tid + i * 256, row = f >> 3, c8 = f & 7;
                uint32_t so = (uint32_t)((buf * 128 + row) * GPH + c8 * 8) * 2;
                cp16(sAu + so, Ag + (size_t)row * E_ + k0 + c8 * 8);
                cp16(sBu + so, Bg + (size_t)row * E_ + k0 + c8 * 8);
            }
            cp_commit();
        }
        const uint32_t abuf = sAu + (uint32_t)(ks & 1) * 128 * GPH * 2;
        const uint32_t bbuf = sBu + (uint32_t)(ks & 1) * 128 * GPH * 2;
#pragma unroll
        for (int kk = 0; kk < 4; kk++) {
            uint32_t af[4][4], bf[4][2];
#pragma unroll
            for (int mi = 0; mi < 4; mi++)
                ldsm4(af[mi][0], af[mi][1], af[mi][2], af[mi][3],
                      abuf + aoff[mi] + kk * 32);
#pragma unroll
            for (int np = 0; np < 2; np++)
                ldsm4(bf[np * 2][0], bf[np * 2][1], bf[np * 2 + 1][0], bf[np * 2 + 1][1],
                      bbuf + boff[np] + kk * 32);
#pragma unroll
            for (int mi = 0; mi < 4; mi++)
#pragma unroll
                for (int ni = 0; ni < 4; ni++)
                    mma16h(acc[mi][ni][0], acc[mi][ni][1], acc[mi][ni][2], acc[mi][ni][3],
                           af[mi][0], af[mi][1], af[mi][2], af[mi][3],
                           bf[ni][0], bf[ni][1]);
        }
    }

    if (bias) {
#pragma unroll
        for (int mi = 0; mi < 4; mi++) {
            int row = bm + wm * 64 + mi * 16 + r4;
#pragma unroll
            for (int ni = 0; ni < 4; ni++) {
                int col = bn + wn * 32 + ni * 8 + 2 * cc;
                float b0 = bias[col], b1 = bias[col + 1];
                *(float2*)(Cf + (size_t)row * E_ + col) =
                    make_float2(acc[mi][ni][0] + b0, acc[mi][ni][1] + b1);
                *(float2*)(Cf + (size_t)(row + 8) * E_ + col) =
                    make_float2(acc[mi][ni][2] + b0, acc[mi][ni][3] + b1);
            }
        }
    } else if (z == 2) {
#pragma unroll
        for (int mi = 0; mi < 4; mi++) {
            int tok = bm + wm * 64 + mi * 16 + r4;
            int bb = tok >> 11, tt = tok & 2047;
#pragma unroll
            for (int ni = 0; ni < 4; ni++) {
                int f = bn + wn * 32 + ni * 8 + 2 * cc;
                int head = f >> 6, nl = f & 63;
                __half* p = Vth + ((size_t)(bb * 8 + head) * 64 + nl) * 2048 + tt;
                p[0]        = __float2half_rn(acc[mi][ni][0]);
                p[2048]     = __float2half_rn(acc[mi][ni][1]);
                p[8]        = __float2half_rn(acc[mi][ni][2]);
                p[2048 + 8] = __float2half_rn(acc[mi][ni][3]);
            }
        }
    } else {
        __half* CH = (z == 0) ? Qh : Kh;
#pragma unroll
        for (int mi = 0; mi < 4; mi++) {
            int row = bm + wm * 64 + mi * 16 + r4;
#pragma unroll
            for (int ni = 0; ni < 4; ni++) {
                int col = bn + wn * 32 + ni * 8 + 2 * cc;
                __half2 h0 = __floats2half2_rn(acc[mi][ni][0], acc[mi][ni][1]);
                __half2 h1 = __floats2half2_rn(acc[mi][ni][2], acc[mi][ni][3]);
                *(__half2*)(CH + (size_t)row * E_ + col)       = h0;
                *(__half2*)(CH + (size_t)(row + 8) * E_ + col) = h1;
            }
        }
    }
}

// ---------------------------------------------------------------------------
// Fused attention, fp16 mma m16n8k16.  CTA = 64 queries of one (b,h),
// 2 CTAs/SM (smem 62KB, regs <=128).  Warp grid 4(m) x 2(n), warp tile m16.
// Split-k PV + direct exp->fp16 A-fragment pack.  One barrier per iter.
// (Empirically best configuration: R13.)
// ---------------------------------------------------------------------------
#define APH 72
__global__ __launch_bounds__(256, 2) void attn_tc(const int* __restrict__ mask)
{
    extern __shared__ char smc[];
    __half* sQ = (__half*)smc;                  // 64*72 halves (9216 B)
    __half* sK = (__half*)(smc + 9216);         // 2*64*72 (18432 B)
    __half* sV = (__half*)(smc + 27648);        // 2*64*72 (V^T rows = headdim)
    float*  sO = (float*)(smc + 46080);         // 64*68 fp32 (17408 B)
    __shared__ float sL[64][2];

    const int tid = threadIdx.x, lane = tid & 31, w = tid >> 5;
    const int wm = w & 3, wn = w >> 2;          // 4(m) x 2(n)
    const int r4 = lane >> 2, cc = lane & 3;
    const int lr = lane & 7, gq = lane >> 3;
    const int qt = blockIdx.x, bh = blockIdx.y;
    const int b = bh >> 3, h = bh & 7;
    const uint32_t sQu = cvta_s(sQ), sKu = cvta_s(sK), sVu = cvta_s(sV);

    const __half* Qg  = g_Qh  + ((size_t)(b * T_ + qt * 64)) * E_ + h * 64;
    const __half* Kg  = g_Kh  + ((size_t)b * T_) * E_ + h * 64;
    const __half* Vtg = g_Vth + (size_t)bh * 64 * T_;

    uint32_t koff[2];
#pragma unroll
    for (int np = 0; np < 2; np++)
        koff[np] = (uint32_t)(((wn * 32 + np * 16 + (gq >> 1) * 8 + lr) * APH
                              + (gq & 1) * 8) * 2);
    uint32_t voff[4];
#pragma unroll
    for (int np = 0; np < 4; np++)
        voff[np] = (uint32_t)(((np * 16 + (gq >> 1) * 8 + lr) * APH
                              + wn * 32 + (gq & 1) * 8) * 2);
    const uint32_t qoff = (uint32_t)(((wm * 16 + (gq & 1) * 8 + lr) * APH
                                     + (gq >> 1) * 8) * 2);

    // group 0: Q tile (64 x 64 halves)
#pragma unroll
    for (int i = 0; i < 2; i++) {
        int f = tid + i * 256, row = f >> 3, c8 = f & 7;
        cp16(sQu + (uint32_t)(row * APH + c8 * 8) * 2, Qg + (size_t)row * E_ + c8 * 8);
    }
    cp_commit();
    // group 1: K tile 0 + V^T tile 0
#pragma unroll
    for (int i = 0; i < 2; i++) {
        int f = tid + i * 256, row = f >> 3, c8 = f & 7;
        cp16(sKu + (uint32_t)(row * APH + c8 * 8) * 2, Kg  + (size_t)row * E_ + c8 * 8);
        cp16(sVu + (uint32_t)(row * APH + c8 * 8) * 2, Vtg + (size_t)row * T_ + c8 * 8);
    }
    cp_commit();

    const int* mrow = mask + (size_t)bh * T_ + qt * 64 + wm * 16;
    float madd[2];
    madd[0] = mrow[r4]     ? 0.f : -INFINITY;
    madd[1] = mrow[r4 + 8] ? 0.f : -INFINITY;

    cp_wait1();
    __syncthreads();
    uint32_t qf[4][4];
#pragma unroll
    for (int kk = 0; kk < 4; kk++)
        ldsm4(qf[kk][0], qf[kk][1], qf[kk][2], qf[kk][3], sQu + qoff + kk * 32);

    float oAcc[8][4];
    float lsum[2] = {0.f, 0.f};
#pragma unroll
    for (int ni = 0; ni < 8; ni++)
#pragma unroll
        for (int j = 0; j < 4; j++) oAcc[ni][j] = 0.f;

    for (int ct = 0; ct < 32; ct++) {
        cp_wait0();
        __syncthreads();
        if (ct < 31) {
            int buf = (ct + 1) & 1;
            const __half* Kp = Kg  + (size_t)(ct + 1) * 64 * E_;
            const __half* Vp = Vtg + (size_t)(ct + 1) * 64;
#pragma unroll
            for (int i = 0; i < 2; i++) {
                int f = tid + i * 256, row = f >> 3, c8 = f & 7;
                uint32_t so = (uint32_t)((buf * 64 + row) * APH + c8 * 8) * 2;
                cp16(sKu + so, Kp + (size_t)row * E_ + c8 * 8);
                cp16(sVu + so, Vp + (size_t)row * T_ + c8 * 8);
            }
            cp_commit();
        }
        const uint32_t kbu = sKu + (uint32_t)(ct & 1) * 64 * APH * 2;
        const uint32_t vbu = sVu + (uint32_t)(ct & 1) * 64 * APH * 2;

        // ---- S = Q @ K^T (m64 n64 k64)
        float sAcc[4][4];
#pragma unroll
        for (int ni = 0; ni < 4; ni++)
#pragma unroll
            for (int j = 0; j < 4; j++) sAcc[ni][j] = 0.f;

#pragma unroll
        for (int kk = 0; kk < 4; kk++) {
            uint32_t bf[4][2];
#pragma unroll
            for (int np = 0; np < 2; np++)
                ldsm4(bf[np * 2][0], bf[np * 2][1], bf[np * 2 + 1][0], bf[np * 2 + 1][1],
                      kbu + koff[np] + kk * 32);
#pragma unroll
            for (int ni = 0; ni < 4; ni++)
                mma16h(sAcc[ni][0], sAcc[ni][1], sAcc[ni][2], sAcc[ni][3],
                       qf[kk][0], qf[kk][1], qf[kk][2], qf[kk][3],
                       bf[ni][0], bf[ni][1]);
        }

        // ---- exp + direct fp16 pack (acc layout == A-frag layout)
        uint32_t pa[4][2];
#pragma unroll
        for (int nb = 0; nb < 4; nb++) {
            float p0 = ex2(fmaf(sAcc[nb][0], SCALE_LOG2E, madd[0]));
            float p1 = ex2(fmaf(sAcc[nb][1], SCALE_LOG2E, madd[0]));
            float p2 = ex2(fmaf(sAcc[nb][2], SCALE_LOG2E, madd[1]));
            float p3 = ex2(fmaf(sAcc[nb][3], SCALE_LOG2E, madd[1]));
            lsum[0] += p0 + p1;
            lsum[1] += p2 + p3;
            pa[nb][0] = packh2(p0, p1);
            pa[nb][1] = packh2(p2, p3);
        }

        // ---- O += P @ V (split-k: warp's 32 context cols = 2 k16 steps)
#pragma unroll
        for (int kb = 0; kb < 2; kb++) {
            uint32_t bf[8][2];
#pragma unroll
            for (int np = 0; np < 4; np++)
                ldsm4(bf[np * 2][0], bf[np * 2][1], bf[np * 2 + 1][0], bf[np * 2 + 1][1],
                      vbu + voff[np] + kb * 32);
            uint32_t a0 = pa[2 * kb][0],     a1 = pa[2 * kb][1];
            uint32_t a2 = pa[2 * kb + 1][0], a3 = pa[2 * kb + 1][1];
#pragma unroll
            for (int ni = 0; ni < 8; ni++)
                mma16h(oAcc[ni][0], oAcc[ni][1], oAcc[ni][2], oAcc[ni][3],
                       a0, a1, a2, a3, bf[ni][0], bf[ni][1]);
        }
    }

    // ---- l reduction (quad lanes) -> sL[row][wn]
#pragma unroll
    for (int rr = 0; rr < 2; rr++) {
        float s = lsum[rr];
        s += __shfl_xor_sync(0xffffffffu, s, 1);
        s += __shfl_xor_sync(0xffffffffu, s, 2);
        if (cc == 0) sL[wm * 16 + r4 + rr * 8][wn] = s;
    }

    // ---- cross-wn O reduction via fp32 smem
    if (wn == 1) {
        int row = wm * 16 + r4;
#pragma unroll
        for (int ni = 0; ni < 8; ni++) {
            *(float2*)(sO + row * 68 + ni * 8 + 2 * cc) =
                make_float2(oAcc[ni][0], oAcc[ni][1]);
            *(float2*)(sO + (row + 8) * 68 + ni * 8 + 2 * cc) =
                make_float2(oAcc[ni][2], oAcc[ni][3]);
        }
    }
    __syncthreads();

    if (wn == 0) {
        __half* Og = g_Oh + ((size_t)(b * T_ + qt * 64)) * E_ + h * 64;
        int row = wm * 16 + r4;
        float inv0 = 1.f / (sL[row][0] + sL[row][1]);
        float inv1 = 1.f / (sL[row + 8][0] + sL[row + 8][1]);
#pragma unroll
        for (int ni = 0; ni < 8; ni++) {
            float2 q0 = *(float2*)(sO + row * 68 + ni * 8 + 2 * cc);
            float2 q1 = *(float2*)(sO + (row + 8) * 68 + ni * 8 + 2 * cc);
            int col = ni * 8 + 2 * cc;
            *(__half2*)(Og + (size_t)row * E_ + col) =
                __floats2half2_rn((oAcc[ni][0] + q0.x) * inv0,
                                  (oAcc[ni][1] + q0.y) * inv0);
            *(__half2*)(Og + (size_t)(row + 8) * E_ + col) =
                __floats2half2_rn((oAcc[ni][2] + q1.x) * inv1,
                                  (oAcc[ni][3] + q1.y) * inv1);
        }
    }
}

// ---------------------------------------------------------------------------
extern "C" void kernel_launch(void* const* d_in, const int* in_sizes, int n_in,
                              void* d_out, int out_size)
{
    const float* x    = (const float*)d_in[0];
    const float* ctx  = (const float*)d_in[1];
    const int*   mask = (const int*)d_in[2];
    const float* Wq   = (const float*)d_in[3];
    const float* Wk   = (const float*)d_in[4];
    const float* Wv   = (const float*)d_in[5];
    const float* Wu   = (const float*)d_in[6];
    const float* bu   = (const float*)d_in[7];
    float* out = (float*)d_out;

    __half *pxh, *pch, *pWh, *pQh, *pKh, *pVth, *pOh;
    cudaGetSymbolAddress((void**)&pxh,  g_xh);
    cudaGetSymbolAddress((void**)&pch,  g_ch);
    cudaGetSymbolAddress((void**)&pWh,  g_Wh);
    cudaGetSymbolAddress((void**)&pQh,  g_Qh);
    cudaGetSymbolAddress((void**)&pKh,  g_Kh);
    cudaGetSymbolAddress((void**)&pVth, g_Vth);
    cudaGetSymbolAddress((void**)&pOh,  g_Oh);

    const int NX = B_ * T_ * E_ / 4;   // 1048576 float4 per tensor
    const int NW = E_ * E_ / 4;        // 65536 float4 per weight
    const int NTOT = 2 * NX + 4 * NW;  // 2359296 -> 9216 blocks
    cvt_all<<<NTOT / 256, 256>>>((const float4*)x, (uint2*)pxh,
                                 (const float4*)ctx, (uint2*)pch,
                                 (const float4*)Wq, (const float4*)Wk,
                                 (const float4*)Wv, (const float4*)Wu,
                                 (uint2*)pWh, NX, NW);

    const int SMEM_G = 4 * 128 * GPH * 2;              // 73728
    const int SMEM_A = 46080 + 64 * 68 * 4;            // 63488
    cudaFuncSetAttribute(gemm_h,  cudaFuncAttributeMaxDynamicSharedMemorySize, SMEM_G);
    cudaFuncSetAttribute(attn_tc, cudaFuncAttributeMaxDynamicSharedMemorySize, SMEM_A);

    // merged Q/K/V projections (fp16; z=2 writes V^T)
    dim3 gQKV(E_ / 128, B_ * T_ / 128, 3);
    gemm_h<<<gQKV, 256, SMEM_G>>>(pxh, pch, pWh, nullptr, nullptr, pQh, pKh, pVth);

    dim3 gA(T_ / 64, B_ * H_);   // (32, 32) = 1024 CTAs, 2 per SM
    attn_tc<<<gA, 256, SMEM_A>>>(mask);

    // output projection (fp32 + bias)
    dim3 gO(E_ / 128, B_ * T_ / 128, 1);
    gemm_h<<<gO, 256, SMEM_G>>>(pOh, nullptr, pWh + 3 * E_ * E_, bu, out,
                                nullptr, nullptr, nullptr);
}